// round 12
// baseline (speedup 1.0000x reference)
#include <cuda_runtime.h>
#include <math.h>

#define TY   50
#define BB   32
#define TXX  400
#define HH   512
#define CTXD 1024
#define DYD  512
#define G4   2048
#define VV   50000
#define VE   50050
#define HCAT 2048

// Output layout: flattened tree leaves of ((hs,cs), ss, atts, dists, Cs, ydecs)
// hs 50*32*512 | cs 50*32*512 | ss 50*32*1024 | atts 50*32*1024 | dists 50*32*400 | Cs 50*32*400 | ydecs 50*32*50050
#define OFF_HS   0LL
#define OFF_CSo  819200LL
#define OFF_SS   1638400LL
#define OFF_ATT  3276800LL
#define OFF_DIS  4915200LL
#define OFF_COV  5555200LL
#define OFF_YD   6195200LL

// ---------- scratch (static device allocations, allowed) ----------
__device__ float g_pctx[(size_t)TXX*BB*CTXD];   // 52.4 MB
__device__ float g_h[BB*HH], g_c[BB*HH];
__device__ float g_h1[BB*HH], g_c1[BB*HH];
__device__ float g_acc[BB*TXX];
__device__ float g_gates[BB*G4];
__device__ float g_hq[BB*CTXD];
__device__ float g_sc[BB*TXX];
__device__ float g_w[BB*TXX];
__device__ float g_att[BB*CTXD];
__device__ float g_ds[BB*HH];
__device__ float g_gg[BB];
__device__ float g_logit[(size_t)VV*BB];        // [v][b], 6.4 MB
__device__ float g_pm[16*BB], g_ps[16*BB];
__device__ float g_M[BB], g_Sinv[BB];

// ---------- helpers ----------
__device__ __forceinline__ float sigf(float x){ return 1.f/(1.f+__expf(-x)); }
__device__ __forceinline__ float tanhfast(float x){
    x = fminf(15.f, fmaxf(-15.f, x));
    float e = __expf(2.f*x);
    return (e-1.f)/(e+1.f);
}
__device__ __forceinline__ float warpSum(float v){
    #pragma unroll
    for(int o=16;o>0;o>>=1) v += __shfl_xor_sync(0xffffffffu, v, o);
    return v;
}
__device__ __forceinline__ float warpMax(float v){
    #pragma unroll
    for(int o=16;o>0;o>>=1) v = fmaxf(v, __shfl_xor_sync(0xffffffffu, v, o));
    return v;
}

// ---------- kernels ----------
__global__ void k_init(const float* __restrict__ h0, const float* __restrict__ c0,
                       const float* __restrict__ cov0){
    int i = blockIdx.x*256 + threadIdx.x;
    if(i < BB*HH){ g_h[i]=h0[i]; g_c[i]=c0[i]; }
    if(i < BB*TXX){ g_acc[i]=cov0[i]; }
}

// pctx[tb,d] = context[tb,:1024] . Wc[d,:1024] + b_att[d]   (4 tb-rows per block)
#define PCTB 4
__global__ void k_pctx(const float* __restrict__ ctx, const float* __restrict__ Wc,
                       const float* __restrict__ batt){
    __shared__ __align__(16) float xs[PCTB][CTXD];
    int tb0 = blockIdx.x*PCTB;
    int d   = blockIdx.y*256 + threadIdx.x;
    for(int i=threadIdx.x; i<PCTB*CTXD; i+=256){
        int r = i >> 10, k = i & 1023;
        xs[r][k] = ctx[(size_t)(tb0+r)*CTXD + k];
    }
    __syncthreads();
    const float4* w4 = (const float4*)(Wc + (size_t)d*CTXD);
    float acc[PCTB];
    #pragma unroll
    for(int r=0;r<PCTB;r++) acc[r]=0.f;
    #pragma unroll 4
    for(int k=0;k<CTXD/4;k++){
        float4 a = w4[k];
        #pragma unroll
        for(int r=0;r<PCTB;r++){
            float4 x = *(const float4*)&xs[r][k*4];
            acc[r] += a.x*x.x + a.y*x.y + a.z*x.z + a.w*x.w;
        }
    }
    float bb = batt[d];
    #pragma unroll
    for(int r=0;r<PCTB;r++)
        g_pctx[(size_t)(tb0+r)*CTXD + d] = acc[r] + bb;
}

// gates[b,j] = x_t[b,:512].Wih[j,:] + h[b,:512].Whh[j,:] + bih[j]+bhh[j]
__global__ void k_gates(const float* __restrict__ x_t, const float* __restrict__ Wih,
                        const float* __restrict__ Whh, const float* __restrict__ bih,
                        const float* __restrict__ bhh){
    __shared__ __align__(16) float xs[DYD];
    __shared__ __align__(16) float hsh[HH];
    int b = blockIdx.y;
    int j = blockIdx.x*256 + threadIdx.x;
    for(int k=threadIdx.x;k<DYD;k+=256) xs[k]=x_t[(size_t)b*DYD+k];
    for(int k=threadIdx.x;k<HH;k+=256) hsh[k]=g_h[b*HH+k];
    __syncthreads();
    const float4* wi=(const float4*)(Wih + (size_t)j*DYD);
    const float4* wh=(const float4*)(Whh + (size_t)j*HH);
    const float4* x4=(const float4*)xs;
    const float4* h4=(const float4*)hsh;
    float acc = bih[j] + bhh[j];
    #pragma unroll 8
    for(int k=0;k<HH/4;k++){
        float4 a=wi[k], x=x4[k];
        acc += a.x*x.x + a.y*x.y + a.z*x.z + a.w*x.w;
        float4 c=wh[k], y=h4[k];
        acc += c.x*y.x + c.y*y.y + c.z*y.z + c.w*y.w;
    }
    g_gates[b*G4 + j] = acc;
}

// first LSTM cell (order i,f,g,o) + mask blend; writes ss output
__global__ void k_cell1(const float* __restrict__ ym_t, float* __restrict__ ss_out){
    int i = blockIdx.x*256 + threadIdx.x;   // 16384
    int b = i >> 9, d = i & 511;
    float gi=g_gates[b*G4+d],      gf=g_gates[b*G4+512+d];
    float gg=g_gates[b*G4+1024+d], go=g_gates[b*G4+1536+d];
    float cp=g_c[i], hp=g_h[i];
    float ym=ym_t[b];
    float c1 = sigf(gf)*cp + sigf(gi)*tanhfast(gg);
    float h1 = sigf(go)*tanhfast(c1);
    h1 = ym*h1 + (1.f-ym)*hp;
    c1 = ym*c1 + (1.f-ym)*cp;
    g_h1[i]=h1; g_c1[i]=c1;
    ss_out[b*1024 + d]       = h1;
    ss_out[b*1024 + 512 + d] = c1;
}

// hq[b,d] = [h1,c1](1024) . Wcomb[d,:1024],  d<1024
__global__ void k_hq(const float* __restrict__ Wcomb){
    __shared__ __align__(16) float s[1024];
    int b = blockIdx.y;
    int d = blockIdx.x*256 + threadIdx.x;   // grid.x=4 -> d<1024
    for(int k=threadIdx.x;k<512;k+=256){ s[k]=g_h1[b*512+k]; s[512+k]=g_c1[b*512+k]; }
    __syncthreads();
    const float4* w4=(const float4*)(Wcomb + (size_t)d*1024);
    const float4* s4=(const float4*)s;
    float acc=0.f;
    #pragma unroll 8
    for(int k=0;k<256;k++){
        float4 a=w4[k], x=s4[k];
        acc += a.x*x.x + a.y*x.y + a.z*x.z + a.w*x.w;
    }
    g_hq[b*1024+d]=acc;
}

// scores[tx,b] = xmask * sum_{c<1024} tanh(pctx + hq + acc*wcov[c]) * Uatt[c]  (warp per pair)
__global__ void k_scores(const float* __restrict__ xmask, const float* __restrict__ wcov,
                         const float* __restrict__ uatt){
    int p    = blockIdx.x*8 + (threadIdx.x >> 5);   // p = tx*32 + b
    int lane = threadIdx.x & 31;
    int b = p & 31, tx = p >> 5;
    float a = g_acc[b*TXX + tx];
    const float* prow = g_pctx + (size_t)p*CTXD;
    const float* hrow = g_hq + b*CTXD;
    float acc = 0.f;
    #pragma unroll 4
    for(int c=lane;c<CTXD;c+=32){
        float u = tanhfast(prow[c] + hrow[c] + a*wcov[c]);
        acc += u * uatt[c];
    }
    acc = warpSum(acc);
    if(lane==0) g_sc[b*TXX + tx] = acc * xmask[tx*BB + b];
}

// masked softmax over Tx per b; writes dists + Cs (pre-update coverage), updates coverage
__global__ void k_smax_tx(const float* __restrict__ xmask, float* __restrict__ dis_out,
                          float* __restrict__ cov_out){
    __shared__ float red[32];
    int b = blockIdx.x, tid = threadIdx.x;  // 512 threads
    float s = (tid < TXX) ? g_sc[b*TXX + tid] : -1e30f;
    float m = warpMax(s);
    if((tid&31)==0) red[tid>>5]=m;
    __syncthreads();
    if(tid<32){ float v=(tid<16)?red[tid]:-1e30f; v=warpMax(v); if(tid==0) red[0]=v; }
    __syncthreads();
    m = red[0];
    float xm = (tid < TXX) ? xmask[tid*BB + b] : 0.f;
    float e  = (tid < TXX) ? __expf(s - m)*xm : 0.f;
    __syncthreads();
    float ss = warpSum(e);
    if((tid&31)==0) red[tid>>5]=ss;
    __syncthreads();
    if(tid<32){ float v=(tid<16)?red[tid]:0.f; v=warpSum(v); if(tid==0) red[0]=v; }
    __syncthreads();
    float inv = 1.f/red[0];
    if(tid < TXX){
        float w = e*inv;
        g_w[b*TXX + tid] = w;
        dis_out[b*TXX + tid] = w;
        float aa = g_acc[b*TXX + tid];
        cov_out[b*TXX + tid] = aa;
        g_acc[b*TXX + tid] = aa + w;
    }
}

// atted[b,c] = sum_tx w[b,tx] * context[tx,b,c],  c<1024
__global__ void k_atted(const float* __restrict__ ctx, float* __restrict__ att_out){
    __shared__ float ws[TXX];
    int b = blockIdx.y;
    int c = blockIdx.x*256 + threadIdx.x;   // grid.x=4 -> c<1024
    for(int k=threadIdx.x;k<TXX;k+=256) ws[k]=g_w[b*TXX+k];
    __syncthreads();
    const float* cb = ctx + (size_t)b*CTXD + c;
    float acc=0.f;
    #pragma unroll 4
    for(int tx=0;tx<TXX;tx++) acc += ws[tx]*cb[(size_t)tx*BB*CTXD];
    g_att[b*CTXD+c]=acc;
    att_out[b*CTXD+c]=acc;
}

// pre[b,j] = h1(512).Ux[j,:512] + atted(1024).Wx[j,:1024] + bx[j]
__global__ void k_pre(const float* __restrict__ Ux, const float* __restrict__ Wx,
                      const float* __restrict__ bx){
    __shared__ __align__(16) float hsh[512];
    __shared__ __align__(16) float ash[1024];
    int b = blockIdx.y;
    int j = blockIdx.x*256 + threadIdx.x;
    for(int k=threadIdx.x;k<512;k+=256)  hsh[k]=g_h1[b*512+k];
    for(int k=threadIdx.x;k<1024;k+=256) ash[k]=g_att[b*CTXD+k];
    __syncthreads();
    const float4* u4=(const float4*)(Ux + (size_t)j*512);
    const float4* w4=(const float4*)(Wx + (size_t)j*1024);
    const float4* h4=(const float4*)hsh;
    const float4* a4=(const float4*)ash;
    float acc = bx[j];
    #pragma unroll 8
    for(int k=0;k<128;k++){
        float4 a=u4[k], x=h4[k];
        acc += a.x*x.x + a.y*x.y + a.z*x.z + a.w*x.w;
    }
    #pragma unroll 8
    for(int k=0;k<256;k++){
        float4 c=w4[k], y=a4[k];
        acc += c.x*y.x + c.y*y.y + c.z*y.z + c.w*y.w;
    }
    g_gates[b*G4 + j] = acc;
}

// second LSTM cell (order i,f,o,c!) + blend; writes hs/cs, updates state
__global__ void k_cell2(const float* __restrict__ ym_t, float* __restrict__ hs_out,
                        float* __restrict__ cs_out){
    int i = blockIdx.x*256 + threadIdx.x;
    int b = i >> 9, d = i & 511;
    float xi=g_gates[b*G4+d],      xf=g_gates[b*G4+512+d];
    float xo=g_gates[b*G4+1024+d], xc=g_gates[b*G4+1536+d];
    float c1=g_c1[i], h1=g_h1[i], ym=ym_t[b];
    float c2 = sigf(xf)*c1 + sigf(xi)*tanhfast(xc);
    float h2 = sigf(xo)*tanhfast(c2);
    c2 = ym*c2 + (1.f-ym)*c1;
    h2 = ym*h2 + (1.f-ym)*h1;
    g_h[i]=h2; g_c[i]=c2;
    hs_out[i]=h2; cs_out[i]=c2;
}

// ds[b,k] = tanh(hcat(2048).w_ds[k,:2048] + b_ds[k]);  g[b] = sigmoid(hcat.v + bv)
__global__ void k_ds_g(const float* __restrict__ x_t, const float* __restrict__ w_ds,
                       const float* __restrict__ b_ds, const float* __restrict__ vvec,
                       const float* __restrict__ bv){
    __shared__ __align__(16) float hc[HCAT];
    __shared__ float red[16];
    int b = blockIdx.x, tid = threadIdx.x;  // 512 threads
    hc[tid]        = g_h[b*512+tid];
    hc[512 + tid]  = g_att[b*CTXD+tid];
    hc[1024 + tid] = g_att[b*CTXD+512+tid];
    hc[1536 + tid] = x_t[(size_t)b*512+tid];
    __syncthreads();
    const float4* w4=(const float4*)(w_ds + (size_t)tid*HCAT);
    const float4* h4=(const float4*)hc;
    float acc = b_ds[tid];
    #pragma unroll 8
    for(int k=0;k<HCAT/4;k++){
        float4 a=w4[k], x=h4[k];
        acc += a.x*x.x + a.y*x.y + a.z*x.z + a.w*x.w;
    }
    g_ds[b*512+tid] = tanhfast(acc);
    float pg = hc[tid]*vvec[tid] + hc[512+tid]*vvec[512+tid]
             + hc[1024+tid]*vvec[1024+tid] + hc[1536+tid]*vvec[1536+tid];
    pg = warpSum(pg);
    if((tid&31)==0) red[tid>>5]=pg;
    __syncthreads();
    if(tid<32){
        float v=(tid<16)?red[tid]:0.f;
        v=warpSum(v);
        if(tid==0) g_gg[b]=sigf(v + bv[0]);
    }
}

// logit[v,b] = ds[b,:512] . w_logit[v,:512] + b_logit[v]
__global__ void __launch_bounds__(128) k_logit(const float* __restrict__ w_logit,
                                               const float* __restrict__ b_logit){
    __shared__ __align__(16) float ds_s[32][128];
    int v0 = blockIdx.x*256 + threadIdx.x;
    int v1 = v0 + 128;
    int v0c = v0 < VV ? v0 : VV-1;
    int v1c = v1 < VV ? v1 : VV-1;
    float acc0[32], acc1[32];
    #pragma unroll
    for(int b=0;b<32;b++){ acc0[b]=0.f; acc1[b]=0.f; }
    for(int ch=0; ch<4; ch++){
        __syncthreads();
        for(int i=threadIdx.x;i<4096;i+=128){
            int b=i>>7, kk=i&127;
            ds_s[b][kk]=g_ds[b*512 + ch*128 + kk];
        }
        __syncthreads();
        const float4* w0=(const float4*)(w_logit + (size_t)v0c*512 + ch*128);
        const float4* w1=(const float4*)(w_logit + (size_t)v1c*512 + ch*128);
        #pragma unroll 1
        for(int k4=0;k4<32;k4++){
            float4 a=w0[k4], c=w1[k4];
            #pragma unroll
            for(int b=0;b<32;b++){
                float4 dv = *(const float4*)&ds_s[b][k4*4];
                acc0[b] += dv.x*a.x + dv.y*a.y + dv.z*a.z + dv.w*a.w;
                acc1[b] += dv.x*c.x + dv.y*c.y + dv.z*c.z + dv.w*c.w;
            }
        }
    }
    if(v0 < VV){
        float bl = b_logit[v0];
        float4* dst = (float4*)(g_logit + (size_t)v0*32);
        #pragma unroll
        for(int q=0;q<8;q++){
            float4 o; o.x=acc0[q*4]+bl; o.y=acc0[q*4+1]+bl; o.z=acc0[q*4+2]+bl; o.w=acc0[q*4+3]+bl;
            dst[q]=o;
        }
    }
    if(v1 < VV){
        float bl = b_logit[v1];
        float4* dst = (float4*)(g_logit + (size_t)v1*32);
        #pragma unroll
        for(int q=0;q<8;q++){
            float4 o; o.x=acc1[q*4]+bl; o.y=acc1[q*4+1]+bl; o.z=acc1[q*4+2]+bl; o.w=acc1[q*4+3]+bl;
            dst[q]=o;
        }
    }
}

// online-softmax partials over v-chunks for all b (coalesced [v][b] reads)
__global__ void k_sm1(){
    __shared__ float sm[8][32], ssum[8][32];
    int chunk = blockIdx.x;
    int tid = threadIdx.x;
    int vi = tid >> 5, b = tid & 31;
    int vstart = chunk*3125, vend = vstart + 3125;
    float m = -1e30f, s = 0.f;
    for(int v = vstart + vi; v < vend; v += 8){
        float x = g_logit[(size_t)v*32 + b];
        if(x > m){ s = s*__expf(m - x) + 1.f; m = x; }
        else s += __expf(x - m);
    }
    sm[vi][b]=m; ssum[vi][b]=s;
    __syncthreads();
    if(vi==0){
        float M=m, S=s;
        #pragma unroll
        for(int k=1;k<8;k++){
            float m2=sm[k][b], s2=ssum[k][b];
            float Mn=fmaxf(M,m2);
            S = S*__expf(M-Mn) + s2*__expf(m2-Mn);
            M = Mn;
        }
        g_pm[chunk*32+b]=M; g_ps[chunk*32+b]=S;
    }
}

__global__ void k_sm2(){
    int b = threadIdx.x;
    if(b >= 32) return;
    float M = g_pm[b], S = g_ps[b];
    for(int k=1;k<16;k++){
        float m2=g_pm[k*32+b], s2=g_ps[k*32+b];
        float Mn=fmaxf(M,m2);
        S = S*__expf(M-Mn) + s2*__expf(m2-Mn);
        M = Mn;
    }
    g_M[b]=M; g_Sinv[b]=1.f/S;
}

// y_dec[b,v] = g[b]*exp(logit-M)/S for v<V, 0 for ext; smem transpose for coalesced I/O
__global__ void k_sm3(float* __restrict__ yd){
    __shared__ float tile[8][33];
    __shared__ float sM[32], sI[32], sG[32];
    int tid = threadIdx.x;
    if(tid<32){ sM[tid]=g_M[tid]; sI[tid]=g_Sinv[tid]; sG[tid]=g_gg[tid]; }
    __syncthreads();
    int vbase = blockIdx.x*256;
    int vi = tid>>5, b = tid&31;
    int bo = tid>>3, vo = tid&7;
    for(int i=0;i<32;i++){
        int v = vbase + i*8 + vi;
        float val = 0.f;
        if(v < VV){
            float x = g_logit[(size_t)v*32 + b];
            val = sG[b]*__expf(x - sM[b])*sI[b];
        }
        tile[vi][b]=val;
        __syncthreads();
        int vw = vbase + i*8 + vo;
        if(vw < VE) yd[(size_t)bo*VE + vw] = tile[vo][bo];
        __syncthreads();
    }
}

// scatter-add (1-g)*watt at xid into y_dec
__global__ void k_scatter(const int* __restrict__ xid, float* __restrict__ yd){
    int i = blockIdx.x*256 + threadIdx.x;
    if(i >= BB*TXX) return;
    int tx = i >> 5, b = i & 31;
    int id = xid[tx*BB + b];
    if(id < 0 || id >= VE) return;
    float val = (1.f - g_gg[b]) * g_w[b*TXX + tx];
    atomicAdd(yd + (size_t)b*VE + id, val);
}

// ---------- host ----------
extern "C" void kernel_launch(void* const* d_in, const int* in_sizes, int n_in,
                              void* d_out, int out_size){
    const float* y_emb   = (const float*)d_in[0];
    const float* context = (const float*)d_in[1];
    const float* h0      = (const float*)d_in[2];   // reverted to original order (R9 confirmed)
    const float* c0      = (const float*)d_in[3];
    const float* x_mask  = (const float*)d_in[4];
    const float* y_mask  = (const float*)d_in[5];
    const float* cov0    = (const float*)d_in[6];
    const float* Wih     = (const float*)d_in[7];
    const float* Whh     = (const float*)d_in[8];
    const float* bih     = (const float*)d_in[9];
    const float* bhh     = (const float*)d_in[10];
    const float* Wx      = (const float*)d_in[11];
    const float* Ux      = (const float*)d_in[12];
    const float* bx      = (const float*)d_in[13];
    const float* Wc      = (const float*)d_in[14];
    const float* b_att   = (const float*)d_in[15];
    const float* Wcomb   = (const float*)d_in[16];
    const float* Uatt    = (const float*)d_in[17];
    const float* Wcov    = (const float*)d_in[18];
    const float* w_ds    = (const float*)d_in[19];
    const float* b_ds    = (const float*)d_in[20];
    const float* w_logit = (const float*)d_in[21];
    const float* b_logit = (const float*)d_in[22];
    const float* vvec    = (const float*)d_in[23];
    const float* bv      = (const float*)d_in[24];
    const int*   xid     = (const int*)d_in[25];
    float* out = (float*)d_out;

    k_init<<<64,256>>>(h0, c0, cov0);
    k_pctx<<<dim3(TXX*BB/PCTB, CTXD/256), 256>>>(context, Wc, b_att);

    for(int t=0; t<TY; t++){
        const float* x_t = y_emb + (size_t)t*BB*DYD;
        const float* ym  = y_mask + (size_t)t*BB;

        k_gates<<<dim3(8,BB),256>>>(x_t, Wih, Whh, bih, bhh);
        k_cell1<<<64,256>>>(ym, out + OFF_SS + (long long)t*BB*2*HH);
        k_hq<<<dim3(4,BB),256>>>(Wcomb);
        k_scores<<<1600,256>>>(x_mask, Wcov, Uatt);
        k_smax_tx<<<BB,512>>>(x_mask,
                              out + OFF_DIS + (long long)t*BB*TXX,
                              out + OFF_COV + (long long)t*BB*TXX);
        k_atted<<<dim3(4,BB),256>>>(context, out + OFF_ATT + (long long)t*BB*CTXD);
        k_pre<<<dim3(8,BB),256>>>(Ux, Wx, bx);
        k_cell2<<<64,256>>>(ym,
                            out + OFF_HS  + (long long)t*BB*HH,
                            out + OFF_CSo + (long long)t*BB*HH);
        k_ds_g<<<BB,512>>>(x_t, w_ds, b_ds, vvec, bv);
        k_logit<<<196,128>>>(w_logit, b_logit);
        k_sm1<<<16,256>>>();
        k_sm2<<<1,32>>>();
        k_sm3<<<196,256>>>(out + OFF_YD + (long long)t*BB*VE);
        k_scatter<<<50,256>>>(xid, out + OFF_YD + (long long)t*BB*VE);
    }
}

// round 13
// speedup vs baseline: 1.2388x; 1.2388x over previous
#include <cuda_runtime.h>
#include <math.h>

#define TY   50
#define BB   32
#define TXX  400
#define HH   512
#define CTXD 1024
#define DYD  512
#define G4   2048
#define VV   50000
#define VE   50050
#define HCAT 2048
#define NCH  196      // k_logit blocks = softmax chunks

// Output layout: flattened tree leaves of ((hs,cs), ss, atts, dists, Cs, ydecs)
#define OFF_HS   0LL
#define OFF_CSo  819200LL
#define OFF_SS   1638400LL
#define OFF_ATT  3276800LL
#define OFF_DIS  4915200LL
#define OFF_COV  5555200LL
#define OFF_YD   6195200LL

// ---------- scratch (static device allocations, allowed) ----------
__device__ float g_pctx[(size_t)TXX*BB*CTXD];   // 52.4 MB
__device__ float g_h[BB*HH], g_c[BB*HH];
__device__ float g_h1[BB*HH], g_c1[BB*HH];
__device__ float g_acc[BB*TXX];
__device__ float g_gates[BB*G4];
__device__ float g_hq[BB*CTXD];
__device__ float g_sc[BB*TXX];
__device__ float g_w[BB*TXX];
__device__ float g_att[BB*CTXD];
__device__ float g_ds[BB*HH];
__device__ float g_gg[BB];
__device__ float g_logit[(size_t)VV*BB];        // [v][b], 6.4 MB
__device__ float g_pm[NCH*BB], g_ps[NCH*BB];

// ---------- helpers ----------
__device__ __forceinline__ float sigf(float x){ return 1.f/(1.f+__expf(-x)); }
__device__ __forceinline__ float tanhfast(float x){   // exact-ish, used in cells/ds
    x = fminf(15.f, fmaxf(-15.f, x));
    float e = __expf(2.f*x);
    return (e-1.f)/(e+1.f);
}
__device__ __forceinline__ float tanh_mufu(float x){  // 1 MUFU op, used in k_scores
    float y;
    asm("tanh.approx.f32 %0, %1;" : "=f"(y) : "f"(x));
    return y;
}
__device__ __forceinline__ float warpSum(float v){
    #pragma unroll
    for(int o=16;o>0;o>>=1) v += __shfl_xor_sync(0xffffffffu, v, o);
    return v;
}
__device__ __forceinline__ float warpMax(float v){
    #pragma unroll
    for(int o=16;o>0;o>>=1) v = fmaxf(v, __shfl_xor_sync(0xffffffffu, v, o));
    return v;
}

// ---------- kernels ----------
__global__ void k_init(const float* __restrict__ h0, const float* __restrict__ c0,
                       const float* __restrict__ cov0){
    int i = blockIdx.x*256 + threadIdx.x;
    if(i < BB*HH){ g_h[i]=h0[i]; g_c[i]=c0[i]; }
    if(i < BB*TXX){ g_acc[i]=cov0[i]; }
}

// pctx[tb,d] = context[tb,:1024] . Wc[d,:1024] + b_att[d]   (8 tb-rows per block)
#define PCTB 8
__global__ void k_pctx(const float* __restrict__ ctx, const float* __restrict__ Wc,
                       const float* __restrict__ batt){
    __shared__ __align__(16) float xs[PCTB][CTXD];
    int tb0 = blockIdx.x*PCTB;
    int d   = blockIdx.y*256 + threadIdx.x;
    for(int i=threadIdx.x; i<PCTB*CTXD; i+=256){
        int r = i >> 10, k = i & 1023;
        xs[r][k] = ctx[(size_t)(tb0+r)*CTXD + k];
    }
    __syncthreads();
    const float4* w4 = (const float4*)(Wc + (size_t)d*CTXD);
    float acc[PCTB];
    #pragma unroll
    for(int r=0;r<PCTB;r++) acc[r]=0.f;
    #pragma unroll 2
    for(int k=0;k<CTXD/4;k++){
        float4 a = w4[k];
        #pragma unroll
        for(int r=0;r<PCTB;r++){
            float4 x = *(const float4*)&xs[r][k*4];
            acc[r] += a.x*x.x + a.y*x.y + a.z*x.z + a.w*x.w;
        }
    }
    float bb = batt[d];
    #pragma unroll
    for(int r=0;r<PCTB;r++)
        g_pctx[(size_t)(tb0+r)*CTXD + d] = acc[r] + bb;
}

// gates[b,j] = x_t[b,:].Wih[j,:] + h[b,:].Whh[j,:] + bih[j]+bhh[j]
__global__ void k_gates(const float* __restrict__ x_t, const float* __restrict__ Wih,
                        const float* __restrict__ Whh, const float* __restrict__ bih,
                        const float* __restrict__ bhh){
    __shared__ __align__(16) float xs[DYD];
    __shared__ __align__(16) float hsh[HH];
    int b = blockIdx.y;
    int j = blockIdx.x*256 + threadIdx.x;
    for(int k=threadIdx.x;k<DYD;k+=256) xs[k]=x_t[(size_t)b*DYD+k];
    for(int k=threadIdx.x;k<HH;k+=256) hsh[k]=g_h[b*HH+k];
    __syncthreads();
    const float4* wi=(const float4*)(Wih + (size_t)j*DYD);
    const float4* wh=(const float4*)(Whh + (size_t)j*HH);
    const float4* x4=(const float4*)xs;
    const float4* h4=(const float4*)hsh;
    float acc = bih[j] + bhh[j];
    #pragma unroll 8
    for(int k=0;k<HH/4;k++){
        float4 a=wi[k], x=x4[k];
        acc += a.x*x.x + a.y*x.y + a.z*x.z + a.w*x.w;
        float4 c=wh[k], y=h4[k];
        acc += c.x*y.x + c.y*y.y + c.z*y.z + c.w*y.w;
    }
    g_gates[b*G4 + j] = acc;
}

// first LSTM cell (order i,f,g,o) + mask blend; writes ss output
__global__ void k_cell1(const float* __restrict__ ym_t, float* __restrict__ ss_out){
    int i = blockIdx.x*256 + threadIdx.x;   // 16384
    int b = i >> 9, d = i & 511;
    float gi=g_gates[b*G4+d],      gf=g_gates[b*G4+512+d];
    float gg=g_gates[b*G4+1024+d], go=g_gates[b*G4+1536+d];
    float cp=g_c[i], hp=g_h[i];
    float ym=ym_t[b];
    float c1 = sigf(gf)*cp + sigf(gi)*tanhfast(gg);
    float h1 = sigf(go)*tanhfast(c1);
    h1 = ym*h1 + (1.f-ym)*hp;
    c1 = ym*c1 + (1.f-ym)*cp;
    g_h1[i]=h1; g_c1[i]=c1;
    ss_out[b*1024 + d]       = h1;
    ss_out[b*1024 + 512 + d] = c1;
}

// hq[b,d] = [h1,c1](1024) . Wcomb[d,:1024],  d<1024
__global__ void k_hq(const float* __restrict__ Wcomb){
    __shared__ __align__(16) float s[1024];
    int b = blockIdx.y;
    int d = blockIdx.x*256 + threadIdx.x;
    for(int k=threadIdx.x;k<512;k+=256){ s[k]=g_h1[b*512+k]; s[512+k]=g_c1[b*512+k]; }
    __syncthreads();
    const float4* w4=(const float4*)(Wcomb + (size_t)d*1024);
    const float4* s4=(const float4*)s;
    float acc=0.f;
    #pragma unroll 8
    for(int k=0;k<256;k++){
        float4 a=w4[k], x=s4[k];
        acc += a.x*x.x + a.y*x.y + a.z*x.z + a.w*x.w;
    }
    g_hq[b*1024+d]=acc;
}

// scores[tx,b] = xmask * sum_c tanh(pctx + hq + acc*wcov) * Uatt[c]  (warp per pair)
__global__ void k_scores(const float* __restrict__ xmask, const float* __restrict__ wcov,
                         const float* __restrict__ uatt){
    int p    = blockIdx.x*8 + (threadIdx.x >> 5);   // p = tx*32 + b
    int lane = threadIdx.x & 31;
    int b = p & 31, tx = p >> 5;
    float a = g_acc[b*TXX + tx];
    const float4* p4 = (const float4*)(g_pctx + (size_t)p*CTXD);
    const float4* h4 = (const float4*)(g_hq + (size_t)b*CTXD);
    const float4* w4 = (const float4*)wcov;
    const float4* u4 = (const float4*)uatt;
    float acc = 0.f;
    #pragma unroll
    for(int it=0; it<8; it++){
        int k = it*32 + lane;
        float4 pp=p4[k], hh=h4[k], ww=w4[k], uu=u4[k];
        acc += tanh_mufu(pp.x+hh.x+a*ww.x)*uu.x;
        acc += tanh_mufu(pp.y+hh.y+a*ww.y)*uu.y;
        acc += tanh_mufu(pp.z+hh.z+a*ww.z)*uu.z;
        acc += tanh_mufu(pp.w+hh.w+a*ww.w)*uu.w;
    }
    acc = warpSum(acc);
    if(lane==0) g_sc[b*TXX + tx] = acc * xmask[tx*BB + b];
}

// masked softmax over Tx per b; writes dists + Cs (pre-update coverage), updates coverage
__global__ void k_smax_tx(const float* __restrict__ xmask, float* __restrict__ dis_out,
                          float* __restrict__ cov_out){
    __shared__ float red[32];
    int b = blockIdx.x, tid = threadIdx.x;  // 512 threads
    float s = (tid < TXX) ? g_sc[b*TXX + tid] : -1e30f;
    float m = warpMax(s);
    if((tid&31)==0) red[tid>>5]=m;
    __syncthreads();
    if(tid<32){ float v=(tid<16)?red[tid]:-1e30f; v=warpMax(v); if(tid==0) red[0]=v; }
    __syncthreads();
    m = red[0];
    float xm = (tid < TXX) ? xmask[tid*BB + b] : 0.f;
    float e  = (tid < TXX) ? __expf(s - m)*xm : 0.f;
    __syncthreads();
    float ss = warpSum(e);
    if((tid&31)==0) red[tid>>5]=ss;
    __syncthreads();
    if(tid<32){ float v=(tid<16)?red[tid]:0.f; v=warpSum(v); if(tid==0) red[0]=v; }
    __syncthreads();
    float inv = 1.f/red[0];
    if(tid < TXX){
        float w = e*inv;
        g_w[b*TXX + tid] = w;
        dis_out[b*TXX + tid] = w;
        float aa = g_acc[b*TXX + tid];
        cov_out[b*TXX + tid] = aa;
        g_acc[b*TXX + tid] = aa + w;
    }
}

// atted[b,c] = sum_tx w[b,tx] * context[tx,b,c],  c<1024
__global__ void k_atted(const float* __restrict__ ctx, float* __restrict__ att_out){
    __shared__ float ws[TXX];
    int b = blockIdx.y;
    int c = blockIdx.x*256 + threadIdx.x;
    for(int k=threadIdx.x;k<TXX;k+=256) ws[k]=g_w[b*TXX+k];
    __syncthreads();
    const float* cb = ctx + (size_t)b*CTXD + c;
    float acc=0.f;
    #pragma unroll 4
    for(int tx=0;tx<TXX;tx++) acc += ws[tx]*cb[(size_t)tx*BB*CTXD];
    g_att[b*CTXD+c]=acc;
    att_out[b*CTXD+c]=acc;
}

// pre[b,j] = h1(512).Ux[j] + atted(1024).Wx[j] + bx[j]
__global__ void k_pre(const float* __restrict__ Ux, const float* __restrict__ Wx,
                      const float* __restrict__ bx){
    __shared__ __align__(16) float hsh[512];
    __shared__ __align__(16) float ash[1024];
    int b = blockIdx.y;
    int j = blockIdx.x*256 + threadIdx.x;
    for(int k=threadIdx.x;k<512;k+=256)  hsh[k]=g_h1[b*512+k];
    for(int k=threadIdx.x;k<1024;k+=256) ash[k]=g_att[b*CTXD+k];
    __syncthreads();
    const float4* u4=(const float4*)(Ux + (size_t)j*512);
    const float4* w4=(const float4*)(Wx + (size_t)j*1024);
    const float4* h4=(const float4*)hsh;
    const float4* a4=(const float4*)ash;
    float acc = bx[j];
    #pragma unroll 8
    for(int k=0;k<128;k++){
        float4 a=u4[k], x=h4[k];
        acc += a.x*x.x + a.y*x.y + a.z*x.z + a.w*x.w;
    }
    #pragma unroll 8
    for(int k=0;k<256;k++){
        float4 c=w4[k], y=a4[k];
        acc += c.x*y.x + c.y*y.y + c.z*y.z + c.w*y.w;
    }
    g_gates[b*G4 + j] = acc;
}

// second LSTM cell (order i,f,o,c!) + blend; writes hs/cs, updates state
__global__ void k_cell2(const float* __restrict__ ym_t, float* __restrict__ hs_out,
                        float* __restrict__ cs_out){
    int i = blockIdx.x*256 + threadIdx.x;
    int b = i >> 9, d = i & 511;
    float xi=g_gates[b*G4+d],      xf=g_gates[b*G4+512+d];
    float xo=g_gates[b*G4+1024+d], xc=g_gates[b*G4+1536+d];
    float c1=g_c1[i], h1=g_h1[i], ym=ym_t[b];
    float c2 = sigf(xf)*c1 + sigf(xi)*tanhfast(xc);
    float h2 = sigf(xo)*tanhfast(c2);
    c2 = ym*c2 + (1.f-ym)*c1;
    h2 = ym*h2 + (1.f-ym)*h1;
    g_h[i]=h2; g_c[i]=c2;
    hs_out[i]=h2; cs_out[i]=c2;
}

// ds[b,k] = tanh(hcat(2048).w_ds[k] + b_ds[k]);  block x==0 also: g[b]=sigmoid(hcat.v+bv)
__global__ void k_ds(const float* __restrict__ x_t, const float* __restrict__ w_ds,
                     const float* __restrict__ b_ds, const float* __restrict__ vvec,
                     const float* __restrict__ bv){
    __shared__ __align__(16) float hc[HCAT];
    __shared__ float red[4];
    int b = blockIdx.y, tid = threadIdx.x;  // 128 threads, grid (4, 32)
    for(int i=tid;i<512;i+=128)  hc[i]       = g_h[b*512+i];
    for(int i=tid;i<1024;i+=128) hc[512+i]   = g_att[b*CTXD+i];
    for(int i=tid;i<512;i+=128)  hc[1536+i]  = x_t[(size_t)b*512+i];
    __syncthreads();
    int k = blockIdx.x*128 + tid;
    const float4* w4=(const float4*)(w_ds + (size_t)k*HCAT);
    const float4* h4=(const float4*)hc;
    float acc = b_ds[k];
    #pragma unroll 8
    for(int i=0;i<HCAT/4;i++){
        float4 a=w4[i], x=h4[i];
        acc += a.x*x.x + a.y*x.y + a.z*x.z + a.w*x.w;
    }
    g_ds[b*512+k] = tanhfast(acc);
    if(blockIdx.x==0){
        float pg = 0.f;
        for(int i=tid;i<HCAT;i+=128) pg += hc[i]*vvec[i];
        pg = warpSum(pg);
        if((tid&31)==0) red[tid>>5]=pg;
        __syncthreads();
        if(tid==0) g_gg[b] = sigf(red[0]+red[1]+red[2]+red[3] + bv[0]);
    }
}

// logit[v,b] = ds[b,:512].w_logit[v,:] + b_logit[v]; epilogue: per-block softmax partials
__global__ void __launch_bounds__(128) k_logit(const float* __restrict__ w_logit,
                                               const float* __restrict__ b_logit){
    __shared__ __align__(16) float ds_s[32][128];
    __shared__ float red[128*33];
    __shared__ float msave[32];
    int tid = threadIdx.x;
    int v0 = blockIdx.x*256 + tid;
    int v1 = v0 + 128;
    int v0c = v0 < VV ? v0 : VV-1;
    int v1c = v1 < VV ? v1 : VV-1;
    bool val0 = v0 < VV, val1 = v1 < VV;
    float acc0[32], acc1[32];
    #pragma unroll
    for(int b=0;b<32;b++){ acc0[b]=0.f; acc1[b]=0.f; }
    for(int ch=0; ch<4; ch++){
        __syncthreads();
        for(int i=tid;i<4096;i+=128){
            int b=i>>7, kk=i&127;
            ds_s[b][kk]=g_ds[b*512 + ch*128 + kk];
        }
        __syncthreads();
        const float4* w0=(const float4*)(w_logit + (size_t)v0c*512 + ch*128);
        const float4* w1=(const float4*)(w_logit + (size_t)v1c*512 + ch*128);
        #pragma unroll 1
        for(int k4=0;k4<32;k4++){
            float4 a=w0[k4], c=w1[k4];
            #pragma unroll
            for(int b=0;b<32;b++){
                float4 dv = *(const float4*)&ds_s[b][k4*4];
                acc0[b] += dv.x*a.x + dv.y*a.y + dv.z*a.z + dv.w*a.w;
                acc1[b] += dv.x*c.x + dv.y*c.y + dv.z*c.z + dv.w*c.w;
            }
        }
    }
    // add bias, store logits [v][b]
    if(val0){
        float bl = b_logit[v0];
        #pragma unroll
        for(int b=0;b<32;b++) acc0[b]+=bl;
        float4* dst = (float4*)(g_logit + (size_t)v0*32);
        #pragma unroll
        for(int q=0;q<8;q++){
            float4 o; o.x=acc0[q*4]; o.y=acc0[q*4+1]; o.z=acc0[q*4+2]; o.w=acc0[q*4+3];
            dst[q]=o;
        }
    }
    if(val1){
        float bl = b_logit[v1];
        #pragma unroll
        for(int b=0;b<32;b++) acc1[b]+=bl;
        float4* dst = (float4*)(g_logit + (size_t)v1*32);
        #pragma unroll
        for(int q=0;q<8;q++){
            float4 o; o.x=acc1[q*4]; o.y=acc1[q*4+1]; o.z=acc1[q*4+2]; o.w=acc1[q*4+3];
            dst[q]=o;
        }
    }
    // ---- fused per-block softmax partials over the 256 v of this block ----
    __syncthreads();
    #pragma unroll
    for(int b=0;b<32;b++){
        float m = -1e30f;
        if(val0) m = acc0[b];
        if(val1) m = fmaxf(m, acc1[b]);
        red[tid*33+b] = m;
    }
    __syncthreads();
    #pragma unroll
    for(int s=64;s>0;s>>=1){
        if(tid < s){
            #pragma unroll
            for(int b=0;b<32;b++)
                red[tid*33+b] = fmaxf(red[tid*33+b], red[(tid+s)*33+b]);
        }
        __syncthreads();
    }
    if(tid<32) msave[tid] = red[tid];
    __syncthreads();
    #pragma unroll
    for(int b=0;b<32;b++){
        float M = msave[b];
        float e = 0.f;
        if(val0) e += __expf(acc0[b]-M);
        if(val1) e += __expf(acc1[b]-M);
        red[tid*33+b] = e;
    }
    __syncthreads();
    #pragma unroll
    for(int s=64;s>0;s>>=1){
        if(tid < s){
            #pragma unroll
            for(int b=0;b<32;b++)
                red[tid*33+b] += red[(tid+s)*33+b];
        }
        __syncthreads();
    }
    if(tid<32){
        g_pm[blockIdx.x*32+tid] = msave[tid];
        g_ps[blockIdx.x*32+tid] = red[tid];
    }
}

// y_dec writer: final softmax reduce (over NCH partials) + scale + coalesced transpose
__global__ void k_sm3(float* __restrict__ yd){
    __shared__ float tile[32][33];
    __shared__ float sM[32], sI[32], sG[32];
    __shared__ float pm[8][32], ps[8][32];
    int tid = threadIdx.x;           // 256 threads
    int b = tid & 31, grp = tid >> 5;
    // reduce NCH partials (8 groups in parallel, then combine)
    float M = -1e30f, S = 0.f;
    for(int ch=grp; ch<NCH; ch+=8){
        float m2 = g_pm[ch*32+b], s2 = g_ps[ch*32+b];
        float Mn = fmaxf(M, m2);
        S = S*__expf(M-Mn) + s2*__expf(m2-Mn);
        M = Mn;
    }
    pm[grp][b]=M; ps[grp][b]=S;
    __syncthreads();
    if(tid < 32){
        float Mf = pm[0][tid], Sf = ps[0][tid];
        #pragma unroll
        for(int k=1;k<8;k++){
            float m2=pm[k][tid], s2=ps[k][tid];
            float Mn=fmaxf(Mf,m2);
            Sf = Sf*__expf(Mf-Mn) + s2*__expf(m2-Mn);
            Mf = Mn;
        }
        sM[tid]=Mf; sI[tid]=1.f/Sf; sG[tid]=g_gg[tid];
    }
    __syncthreads();
    int vbase = blockIdx.x*256;
    for(int vt=0; vt<8; vt++){
        int v0t = vbase + vt*32;
        #pragma unroll
        for(int pass=0;pass<4;pass++){
            int vr = pass*8 + (tid>>5);
            int v  = v0t + vr;
            int bb = tid & 31;
            float val = 0.f;
            if(v < VV)
                val = sG[bb]*__expf(g_logit[(size_t)v*32+bb]-sM[bb])*sI[bb];
            tile[vr][bb] = val;
        }
        __syncthreads();
        #pragma unroll
        for(int pass=0;pass<4;pass++){
            int br = pass*8 + (tid>>5);
            int vl = tid & 31;
            int vw = v0t + vl;
            if(vw < VE) yd[(size_t)br*VE + vw] = tile[vl][br];
        }
        __syncthreads();
    }
}

// scatter-add (1-g)*watt at xid into y_dec
__global__ void k_scatter(const int* __restrict__ xid, float* __restrict__ yd){
    int i = blockIdx.x*256 + threadIdx.x;
    if(i >= BB*TXX) return;
    int tx = i >> 5, b = i & 31;
    int id = xid[tx*BB + b];
    if(id < 0 || id >= VE) return;
    float val = (1.f - g_gg[b]) * g_w[b*TXX + tx];
    atomicAdd(yd + (size_t)b*VE + id, val);
}

// ---------- host ----------
extern "C" void kernel_launch(void* const* d_in, const int* in_sizes, int n_in,
                              void* d_out, int out_size){
    const float* y_emb   = (const float*)d_in[0];
    const float* context = (const float*)d_in[1];
    const float* h0      = (const float*)d_in[2];
    const float* c0      = (const float*)d_in[3];
    const float* x_mask  = (const float*)d_in[4];
    const float* y_mask  = (const float*)d_in[5];
    const float* cov0    = (const float*)d_in[6];
    const float* Wih     = (const float*)d_in[7];
    const float* Whh     = (const float*)d_in[8];
    const float* bih     = (const float*)d_in[9];
    const float* bhh     = (const float*)d_in[10];
    const float* Wx      = (const float*)d_in[11];
    const float* Ux      = (const float*)d_in[12];
    const float* bx      = (const float*)d_in[13];
    const float* Wc      = (const float*)d_in[14];
    const float* b_att   = (const float*)d_in[15];
    const float* Wcomb   = (const float*)d_in[16];
    const float* Uatt    = (const float*)d_in[17];
    const float* Wcov    = (const float*)d_in[18];
    const float* w_ds    = (const float*)d_in[19];
    const float* b_ds    = (const float*)d_in[20];
    const float* w_logit = (const float*)d_in[21];
    const float* b_logit = (const float*)d_in[22];
    const float* vvec    = (const float*)d_in[23];
    const float* bv      = (const float*)d_in[24];
    const int*   xid     = (const int*)d_in[25];
    float* out = (float*)d_out;

    k_init<<<64,256>>>(h0, c0, cov0);
    k_pctx<<<dim3(TXX*BB/PCTB, CTXD/256), 256>>>(context, Wc, b_att);

    for(int t=0; t<TY; t++){
        const float* x_t = y_emb + (size_t)t*BB*DYD;
        const float* ym  = y_mask + (size_t)t*BB;

        k_gates<<<dim3(8,BB),256>>>(x_t, Wih, Whh, bih, bhh);
        k_cell1<<<64,256>>>(ym, out + OFF_SS + (long long)t*BB*2*HH);
        k_hq<<<dim3(4,BB),256>>>(Wcomb);
        k_scores<<<1600,256>>>(x_mask, Wcov, Uatt);
        k_smax_tx<<<BB,512>>>(x_mask,
                              out + OFF_DIS + (long long)t*BB*TXX,
                              out + OFF_COV + (long long)t*BB*TXX);
        k_atted<<<dim3(4,BB),256>>>(context, out + OFF_ATT + (long long)t*BB*CTXD);
        k_pre<<<dim3(8,BB),256>>>(Ux, Wx, bx);
        k_cell2<<<64,256>>>(ym,
                            out + OFF_HS  + (long long)t*BB*HH,
                            out + OFF_CSo + (long long)t*BB*HH);
        k_ds<<<dim3(4,BB),128>>>(x_t, w_ds, b_ds, vvec, bv);
        k_logit<<<NCH,128>>>(w_logit, b_logit);
        k_sm3<<<NCH,256>>>(out + OFF_YD + (long long)t*BB*VE);
        k_scatter<<<50,256>>>(xid, out + OFF_YD + (long long)t*BB*VE);
    }
}